// round 15
// baseline (speedup 1.0000x reference)
#include <cuda_runtime.h>
#include <math.h>
#include <float.h>

#define MAXBT 1024
__device__ float g_loss_part[MAXBT];
__device__ float g_lossc_part[MAXBT];
__device__ unsigned int g_count;

typedef unsigned long long u64;

#define NBINS 64
#define XMINV (-4.0f)
#define BINW  (0.125f)
#define INVW  (8.0f)
#define NPTS  1024
#define MAXPAIR 544   // (1024 + 64 pad) / 2
#define NWARP 32

__device__ __forceinline__ u64 pk2(float lo, float hi) {
    u64 r; asm("mov.b64 %0, {%1,%2};" : "=l"(r) : "f"(lo), "f"(hi)); return r;
}
__device__ __forceinline__ void upk2(float& lo, float& hi, u64 v) {
    asm("mov.b64 {%0,%1}, %2;" : "=f"(lo), "=f"(hi) : "l"(v));
}
__device__ __forceinline__ u64 ffma2(u64 a, u64 b, u64 c) {
    u64 d; asm("fma.rn.f32x2 %0, %1, %2, %3;" : "=l"(d) : "l"(a), "l"(b), "l"(c)); return d;
}

__device__ __forceinline__ float sl1(float a, float b) {
    float d = fabsf(a - b);
    return d < 1.0f ? 0.5f * d * d : d - 0.5f;
}

// Embed low 10 bits (pair id) into a float key's truncated mantissa.
__device__ __forceinline__ float embed10(float d, unsigned m2) {
    return __uint_as_float((__float_as_uint(d) & 0xFFFFFC00u) | m2);
}

__device__ __forceinline__ float blockReduceSum(float v, float* red) {
    #pragma unroll
    for (int o = 16; o > 0; o >>= 1)
        v += __shfl_down_sync(0xffffffffu, v, o);
    int lane = threadIdx.x & 31;
    int wid  = threadIdx.x >> 5;
    __syncthreads();
    if (lane == 0) red[wid] = v;
    __syncthreads();
    if (wid == 0) {
        v = (lane < (int)(blockDim.x >> 5)) ? red[lane] : 0.0f;
        #pragma unroll
        for (int o = 16; o > 0; o >>= 1)
            v += __shfl_down_sync(0xffffffffu, v, o);
    }
    return v;
}

// One CTA per (b,t) tile. Targets counting-sorted into 64 x-bins (padded to
// even, tn=1e30 sentinels), paired f32x2 layout. Preds bin-sorted. Warps get
// EQUAL-ESTIMATED-WORK contiguous chunks of the sorted pred array (work est:
// targets within +-2 bins), processed in 32-pred groups with warp-uniform
// windows + ballot expansion. Exact prune: dist^2 >= (tx-xx)^2 at bin edges.
__global__ __launch_bounds__(1024, 1)
void nn_loss_kernel(const float* __restrict__ X,
                    const float* __restrict__ T,
                    const float* __restrict__ W,
                    float* __restrict__ out,
                    int BT, int B)
{
    extern __shared__ char smem[];
    float4* sA  = (float4*)smem;                     //  8704 B
    float4* sB  = sA + MAXPAIR;                      //  8704 B
    float4* xs  = sB + MAXPAIR;                      // 16384 B sorted preds
    int*   binSt = (int*)(xs + NPTS);                // 65
    int*   curT  = binSt + 65;                       // 64
    int*   curP  = curT + NBINS;                     // 64
    int*   cntT  = curP + NBINS;                     // 64
    int*   cntP  = cntT + NBINS;                     // 64
    int*   pSt   = cntP + NBINS;                     // 64
    int*   warpB = pSt + NBINS;                      // 33
    float* Cw    = (float*)(warpB + 34);             // 65
    float* red   = Cw + 65;                          // 32
    __shared__ int isLast;

    const int bt  = blockIdx.x;
    const int tid = threadIdx.x;
    const float* Xb = X + (size_t)bt * NPTS * 3;
    const float* Tb = T + (size_t)bt * NPTS * 3;

    // ---- Stage 1: load, zero, sentinels ----
    float t0 = Tb[tid * 3 + 0], t1 = Tb[tid * 3 + 1], t2 = Tb[tid * 3 + 2];
    float x0 = Xb[tid * 3 + 0], x1 = Xb[tid * 3 + 1], x2 = Xb[tid * 3 + 2];
    float tn = fmaf(t0, t0, fmaf(t1, t1, t2 * t2));
    float xn = fmaf(x0, x0, fmaf(x1, x1, x2 * x2));

    if (tid < NBINS) { cntT[tid] = 0; }
    else if (tid < 2 * NBINS) { cntP[tid - NBINS] = 0; }
    for (int i = tid; i < MAXPAIR; i += NPTS) {
        sA[i] = make_float4(0.f, 0.f, 0.f, 0.f);
        sB[i] = make_float4(0.f, 0.f, 1e30f, 1e30f);
    }
    __syncthreads();

    int tbin = min(max((int)((t0 - XMINV) * INVW), 0), NBINS - 1);
    int pbin = min(max((int)((x0 - XMINV) * INVW), 0), NBINS - 1);
    atomicAdd(&cntT[tbin], 1);
    atomicAdd(&cntP[pbin], 1);
    __syncthreads();

    // ---- Stage 2: prefixes + work estimate (thread 0) ----
    if (tid == 0) {
        int start = 0, ps = 0;
        float c = 0.0f;
        #pragma unroll
        for (int b = 0; b < NBINS; ++b) {
            binSt[b] = start;
            start += (cntT[b] + 1) & ~1;
            pSt[b] = ps;
            ps += cntP[b];
            curT[b] = binSt[b];
            curP[b] = pSt[b];
            // work estimate: preds in bin * targets within +-2 bins
            int lo = max(b - 2, 0), hi = min(b + 2, NBINS - 1);
            int wt = 0;
            for (int k = lo; k <= hi; ++k) wt += cntT[k];
            Cw[b] = c;
            c += (float)cntP[b] * (float)(wt + 4);
        }
        binSt[NBINS] = start;
        Cw[NBINS] = c;
    }
    __syncthreads();

    // ---- Stage 3: scatter (targets + preds) ----
    {
        int slot = atomicAdd(&curT[tbin], 1);
        int m2 = slot >> 1, p = slot & 1;
        float* A  = (float*)&sA[m2];
        float* Bp = (float*)&sB[m2];
        A[p]      = -2.0f * t0;
        A[2 + p]  = -2.0f * t1;
        Bp[p]     = -2.0f * t2;
        Bp[2 + p] = tn;
        int ps = atomicAdd(&curP[pbin], 1);
        xs[ps] = make_float4(x0, x1, x2, xn);
    }

    // ---- Stage 3b: equal-work warp boundaries (parallel search) ----
    if (tid == 0) warpB[0] = 0;
    if (tid == NWARP) warpB[NWARP] = NPTS;
    if (tid >= 1 && tid < NWARP) {
        float targ = Cw[NBINS] * (float)tid / (float)NWARP;
        int b = 0;
        while (b < NBINS - 1 && Cw[b + 1] < targ) ++b;
        float binw = Cw[b + 1] - Cw[b];
        float frac = (binw > 0.0f) ? (targ - Cw[b]) / binw : 0.0f;
        int off = min(cntP[b], (int)(frac * (float)cntP[b]));
        warpB[tid] = pSt[b] + off;
    }
    __syncthreads();
    if (tid == 0) {   // enforce monotone
        #pragma unroll
        for (int w = 1; w <= NWARP; ++w)
            if (warpB[w] < warpB[w - 1]) warpB[w] = warpB[w - 1];
    }
    __syncthreads();

    // ---- Stage 4: balanced warp-uniform pruned scan ----
    const ulonglong2* pA = (const ulonglong2*)sA;
    const ulonglong2* pB = (const ulonglong2*)sB;
    const int w    = tid >> 5;
    const int lane = tid & 31;
    const int wS = warpB[w], wE = warpB[w + 1];

    float ssum = 0.0f;

    for (int base = wS; base < wE; base += 32) {
        int pi = base + lane;
        bool act = pi < wE;
        int pc = act ? pi : (wE - 1);
        float4 xv = xs[pc];
        float xx = xv.x, xn2 = xv.w;
        u64 X0 = pk2(xv.x, xv.x), X1 = pk2(xv.y, xv.y), X2 = pk2(xv.z, xv.z);

        float bestE = FLT_MAX, bestO = FLT_MAX;

        auto scan_range = [&](int m2s, int m2e) {
            #pragma unroll 4
            for (int m2 = m2s; m2 < m2e; ++m2) {
                ulonglong2 a = pA[m2];
                ulonglong2 c = pB[m2];
                u64 dp = ffma2(X0, a.x, ffma2(X1, a.y, ffma2(X2, c.x, c.y)));
                float d0, d1;
                upk2(d0, d1, dp);
                bestE = fminf(bestE, embed10(d0, (unsigned)m2));
                bestO = fminf(bestO, embed10(d1, (unsigned)m2));
            }
        };

        int myb = min(max((int)((xx - XMINV) * INVW), 0), NBINS - 1);
        int wlo = __shfl_sync(0xffffffffu, myb, 0);
        int whi = __shfl_sync(0xffffffffu, myb, 31);

        scan_range(binSt[wlo] >> 1, binSt[whi + 1] >> 1);

        int r = whi + 1, l = wlo - 1;
        for (;;) {
            float bk = fminf(bestE, bestO);
            bool needR = false, needL = false;
            if (r < NBINS) {
                float dx = fmaxf((XMINV + (float)r * BINW) - xx, 0.0f);
                needR = fmaf(dx, dx, -xn2) <= bk;
            }
            if (l >= 0) {
                float dx = fmaxf(xx - (XMINV + (float)(l + 1) * BINW), 0.0f);
                needL = fmaf(dx, dx, -xn2) <= bk;
            }
            bool anyR = __any_sync(0xffffffffu, needR) && (r < NBINS);
            bool anyL = __any_sync(0xffffffffu, needL) && (l >= 0);
            if (!anyR && !anyL) break;
            if (anyR) { scan_range(binSt[r] >> 1, binSt[r + 1] >> 1); ++r; }
            if (anyL) { scan_range(binSt[l] >> 1, binSt[l + 1] >> 1); --l; }
        }

        // decode winner + smooth-L1
        float k = bestE; int h = 0;
        if (bestO < bestE) { k = bestO; h = 1; }
        int m2 = (int)(__float_as_uint(k) & 1023u);
        const float* Af = (const float*)&sA[m2];
        const float* Bf = (const float*)&sB[m2];
        float sv = sl1(xv.x, -0.5f * Af[h])
                 + sl1(xv.y, -0.5f * Af[2 + h])
                 + sl1(xv.z, -0.5f * Bf[h]);
        if (act) ssum += sv;
    }

    // ---- Reductions (coords are tid-based from stage 1) ----
    float S   = blockReduceSum(ssum, red);
    float sx0 = blockReduceSum(x0, red);
    float sx1 = blockReduceSum(x1, red);
    float sx2 = blockReduceSum(x2, red);
    float st0 = blockReduceSum(t0, red);
    float st1 = blockReduceSum(t1, red);
    float st2 = blockReduceSum(t2, red);

    if (tid == 0) {
        g_loss_part[bt] = W[bt] * S;
        float inv = 1.0f / (float)NPTS;
        g_lossc_part[bt] = sl1(sx0 * inv, st0 * inv)
                         + sl1(sx1 * inv, st1 * inv)
                         + sl1(sx2 * inv, st2 * inv);
        __threadfence();
        unsigned int prev = atomicAdd(&g_count, 1u);
        isLast = (prev == (unsigned int)(gridDim.x - 1)) ? 1 : 0;
    }
    __syncthreads();

    if (isLast && tid < 32) {
        __threadfence();
        float v1 = 0.0f, v2 = 0.0f;
        for (int i = tid; i < BT; i += 32) {
            v1 += g_loss_part[i];
            v2 += g_lossc_part[i];
        }
        #pragma unroll
        for (int o = 16; o > 0; o >>= 1) {
            v1 += __shfl_down_sync(0xffffffffu, v1, o);
            v2 += __shfl_down_sync(0xffffffffu, v2, o);
        }
        if (tid == 0) {
            out[0] = v1 / (3.0f * (float)NPTS * (float)B);
            out[1] = v2 / ((float)B * 3.0f);
            g_count = 0;
        }
    }
}

extern "C" void kernel_launch(void* const* d_in, const int* in_sizes, int n_in,
                              void* d_out, int out_size)
{
    const float* X = (const float*)d_in[0];   // [B,T,N,3]
    const float* T = (const float*)d_in[1];   // [B,T,N,3]
    const float* W = (const float*)d_in[2];   // [B,T]
    float* out = (float*)d_out;

    const int BT = in_sizes[2];               // 112
    const int B  = 4;

    size_t smem = (size_t)MAXPAIR * 2 * sizeof(float4)
                + (size_t)NPTS * sizeof(float4)
                + 4096;   // int/float bookkeeping arrays
    nn_loss_kernel<<<BT, NPTS, smem>>>(X, T, W, out, BT, B);
}

// round 17
// speedup vs baseline: 1.1836x; 1.1836x over previous
#include <cuda_runtime.h>
#include <math.h>
#include <float.h>

#define MAXBT 1024
__device__ float g_s  [MAXBT];
__device__ float g_px0[MAXBT];
__device__ float g_px1[MAXBT];
__device__ float g_px2[MAXBT];
__device__ float g_pt0[MAXBT];
__device__ float g_pt1[MAXBT];
__device__ float g_pt2[MAXBT];
__device__ unsigned int g_count;

typedef unsigned long long u64;

#define NBINS 64
#define XMINV (-4.0f)
#define BINW  (0.125f)
#define INVW  (8.0f)
#define NPTS  1024
#define MAXPAIR 544    // (1024 + 64 pad) / 2
#define XS_CAP 832     // >= 775 + 31 pad, multiple of 32

__device__ __forceinline__ u64 pk2(float lo, float hi) {
    u64 r; asm("mov.b64 %0, {%1,%2};" : "=l"(r) : "f"(lo), "f"(hi)); return r;
}
__device__ __forceinline__ void upk2(float& lo, float& hi, u64 v) {
    asm("mov.b64 {%0,%1}, %2;" : "=f"(lo), "=f"(hi) : "l"(v));
}
__device__ __forceinline__ u64 ffma2(u64 a, u64 b, u64 c) {
    u64 d; asm("fma.rn.f32x2 %0, %1, %2, %3;" : "=l"(d) : "l"(a), "l"(b), "l"(c)); return d;
}

__device__ __forceinline__ float sl1(float a, float b) {
    float d = fabsf(a - b);
    return d < 1.0f ? 0.5f * d * d : d - 0.5f;
}

__device__ __forceinline__ float warpSum(float v) {
    #pragma unroll
    for (int o = 16; o > 0; o >>= 1)
        v += __shfl_down_sync(0xffffffffu, v, o);
    return v;
}

// Embed low 10 bits (pair id) into a float key's truncated mantissa.
__device__ __forceinline__ float embed10(float d, unsigned m2) {
    return __uint_as_float((__float_as_uint(d) & 0xFFFFFC00u) | m2);
}

// Flat-balanced binned NN loss: 148 CTAs x 1024 threads; CTA owns 775
// consecutive preds spanning <=2 tiles. Both tiles' targets counting-sorted
// into 64 x-bins in separate smem banks (paired f32x2 layout, tn=1e30
// sentinels in pad slots). CTA's preds bin-sorted per bank; lo section padded
// to a multiple of 32 so every warp is bank/tile-uniform. Scan = R14
// warp-uniform window + ballot expansion (exact bound dist^2 >= (tx-xx)^2).
__global__ __launch_bounds__(1024, 1)
void nn_loss_kernel(const float* __restrict__ X,
                    const float* __restrict__ T,
                    const float* __restrict__ W,
                    float* __restrict__ out,
                    int BT, int B, int totalUnits, int unitsPerCta)
{
    extern __shared__ char smem[];
    float4* sA0 = (float4*)smem;            // bank0 targets
    float4* sB0 = sA0 + MAXPAIR;
    float4* sA1 = sB0 + MAXPAIR;            // bank1 targets
    float4* sB1 = sA1 + MAXPAIR;
    float4* xs  = sB1 + MAXPAIR;            // sorted preds (XS_CAP)
    int* cntT0  = (int*)(xs + XS_CAP);      // 64
    int* cntT1  = cntT0 + NBINS;            // 64
    int* binSt0 = cntT1 + NBINS;            // 65
    int* binSt1 = binSt0 + 65;              // 65
    int* curT0  = binSt1 + 65;              // 64
    int* curT1  = curT0 + NBINS;            // 64
    int* cntP0  = curT1 + NBINS;            // 64
    int* cntP1  = cntP0 + NBINS;            // 64
    int* curP0  = cntP1 + NBINS;            // 64
    int* curP1  = curP0 + NBINS;            // 64
    __shared__ int sCntLo, sPadLo, sTotal, isLast;

    const int tid = threadIdx.x;
    const int bid = blockIdx.x;

    int uStart = bid * unitsPerCta;
    int myU = totalUnits - uStart;
    if (myU > unitsPerCta) myU = unitsPerCta;
    if (myU < 0) myU = 0;
    const int tileLo = uStart >> 10;
    const int tileHi = (myU > 0) ? ((uStart + myU - 1) >> 10) : tileLo;
    const bool twoTiles = (tileHi != tileLo);

    // ---- Stage 0: zero counters, sentinel-init target banks ----
    if (tid < NBINS)            { cntT0[tid] = 0; cntT1[tid] = 0; }
    else if (tid < 2 * NBINS)   { cntP0[tid - NBINS] = 0; cntP1[tid - NBINS] = 0; }
    for (int i = tid; i < MAXPAIR; i += 1024) {
        sA0[i] = make_float4(0.f, 0.f, 0.f, 0.f);
        sB0[i] = make_float4(0.f, 0.f, 1e30f, 1e30f);
        sA1[i] = make_float4(0.f, 0.f, 0.f, 0.f);
        sB1[i] = make_float4(0.f, 0.f, 1e30f, 1e30f);
    }
    __syncthreads();

    // ---- Stage 1: load + histogram ----
    const float* TbLo = T + (size_t)tileLo * NPTS * 3;
    float tl0 = TbLo[tid * 3 + 0], tl1 = TbLo[tid * 3 + 1], tl2 = TbLo[tid * 3 + 2];
    int tbinLo = min(max((int)((tl0 - XMINV) * INVW), 0), NBINS - 1);
    atomicAdd(&cntT0[tbinLo], 1);

    float th0 = 0, th1 = 0, th2 = 0; int tbinHi = 0;
    if (twoTiles) {
        const float* TbHi = T + (size_t)tileHi * NPTS * 3;
        th0 = TbHi[tid * 3 + 0]; th1 = TbHi[tid * 3 + 1]; th2 = TbHi[tid * 3 + 2];
        tbinHi = min(max((int)((th0 - XMINV) * INVW), 0), NBINS - 1);
        atomicAdd(&cntT1[tbinHi], 1);
    }

    float px = 0, py = 0, pz = 0, pxn = 0; int pbin = 0, pbank = 0;
    if (tid < myU) {
        int u = uStart + tid;
        px = X[(size_t)u * 3 + 0];
        py = X[(size_t)u * 3 + 1];
        pz = X[(size_t)u * 3 + 2];
        pxn = fmaf(px, px, fmaf(py, py, pz * pz));
        pbank = ((u >> 10) == tileLo) ? 0 : 1;
        pbin = min(max((int)((px - XMINV) * INVW), 0), NBINS - 1);
        atomicAdd(pbank ? &cntP1[pbin] : &cntP0[pbin], 1);
    }
    __syncthreads();

    // ---- Stage 2: prefix sums (thread 0) ----
    if (tid == 0) {
        int st = 0;
        #pragma unroll
        for (int b = 0; b < NBINS; ++b) { binSt0[b] = st; curT0[b] = st; st += (cntT0[b] + 1) & ~1; }
        binSt0[NBINS] = st;
        st = 0;
        #pragma unroll
        for (int b = 0; b < NBINS; ++b) { binSt1[b] = st; curT1[b] = st; st += (cntT1[b] + 1) & ~1; }
        binSt1[NBINS] = st;
        int ps = 0;
        #pragma unroll
        for (int b = 0; b < NBINS; ++b) { curP0[b] = ps; ps += cntP0[b]; }
        sCntLo = ps;
        int padLo = (ps + 31) & ~31;
        sPadLo = padLo;
        ps = 0;
        #pragma unroll
        for (int b = 0; b < NBINS; ++b) { curP1[b] = padLo + ps; ps += cntP1[b]; }
        sTotal = padLo + ps;
    }
    __syncthreads();

    // ---- Stage 3: scatter ----
    {
        float tn = fmaf(tl0, tl0, fmaf(tl1, tl1, tl2 * tl2));
        int slot = atomicAdd(&curT0[tbinLo], 1);
        int m2 = slot >> 1, p = slot & 1;
        float* A  = (float*)&sA0[m2];
        float* Bp = (float*)&sB0[m2];
        A[p] = -2.0f * tl0;  A[2 + p] = -2.0f * tl1;
        Bp[p] = -2.0f * tl2; Bp[2 + p] = tn;
    }
    if (twoTiles) {
        float tn = fmaf(th0, th0, fmaf(th1, th1, th2 * th2));
        int slot = atomicAdd(&curT1[tbinHi], 1);
        int m2 = slot >> 1, p = slot & 1;
        float* A  = (float*)&sA1[m2];
        float* Bp = (float*)&sB1[m2];
        A[p] = -2.0f * th0;  A[2 + p] = -2.0f * th1;
        Bp[p] = -2.0f * th2; Bp[2 + p] = tn;
    }
    if (tid < myU) {
        int slot = atomicAdd(pbank ? &curP1[pbin] : &curP0[pbin], 1);
        xs[slot] = make_float4(px, py, pz, pxn);
    }
    __syncthreads();
    if (tid >= sCntLo && tid < sPadLo)
        xs[tid] = xs[sCntLo > 0 ? sCntLo - 1 : 0];
    __syncthreads();

    // ---- Stage 4: warp-uniform pruned scan (one slot per thread) ----
    const int cntLo = sCntLo, padLo = sPadLo, total = sTotal;
    const int warpBase = tid & ~31;

    if (warpBase < total) {
        const int bank = (warpBase >= padLo) ? 1 : 0;
        const ulonglong2* pA = (const ulonglong2*)(bank ? sA1 : sA0);
        const ulonglong2* pB = (const ulonglong2*)(bank ? sB1 : sB0);
        const int* binSt = bank ? binSt1 : binSt0;
        const int tileW = bank ? tileHi : tileLo;

        int slot = min(tid, total - 1);
        bool act = (tid < total) && !(bank == 0 && tid >= cntLo);

        float4 xv = xs[slot];
        float xx = xv.x, xn2 = xv.w;
        u64 X0 = pk2(xv.x, xv.x), X1 = pk2(xv.y, xv.y), X2 = pk2(xv.z, xv.z);

        float bestE = FLT_MAX, bestO = FLT_MAX;

        auto scan_range = [&](int m2s, int m2e) {
            #pragma unroll 4
            for (int m2 = m2s; m2 < m2e; ++m2) {
                ulonglong2 a = pA[m2];
                ulonglong2 c = pB[m2];
                u64 dp = ffma2(X0, a.x, ffma2(X1, a.y, ffma2(X2, c.x, c.y)));
                float d0, d1;
                upk2(d0, d1, dp);
                bestE = fminf(bestE, embed10(d0, (unsigned)m2));
                bestO = fminf(bestO, embed10(d1, (unsigned)m2));
            }
        };

        int myb = min(max((int)((xx - XMINV) * INVW), 0), NBINS - 1);
        int wlo = __shfl_sync(0xffffffffu, myb, 0);
        int whi = __shfl_sync(0xffffffffu, myb, 31);

        scan_range(binSt[wlo] >> 1, binSt[whi + 1] >> 1);

        int r = whi + 1, l = wlo - 1;
        for (;;) {
            float bk = fminf(bestE, bestO);
            bool needR = false, needL = false;
            if (r < NBINS) {
                float dx = fmaxf((XMINV + (float)r * BINW) - xx, 0.0f);
                needR = fmaf(dx, dx, -xn2) <= bk;
            }
            if (l >= 0) {
                float dx = fmaxf(xx - (XMINV + (float)(l + 1) * BINW), 0.0f);
                needL = fmaf(dx, dx, -xn2) <= bk;
            }
            bool anyR = __any_sync(0xffffffffu, needR) && (r < NBINS);
            bool anyL = __any_sync(0xffffffffu, needL) && (l >= 0);
            if (!anyR && !anyL) break;
            if (anyR) { scan_range(binSt[r] >> 1, binSt[r + 1] >> 1); ++r; }
            if (anyL) { scan_range(binSt[l] >> 1, binSt[l + 1] >> 1); --l; }
        }

        float k = bestE; int h = 0;
        if (bestO < bestE) { k = bestO; h = 1; }
        int m2 = (int)(__float_as_uint(k) & 1023u);
        const float4* bA = bank ? sA1 : sA0;
        const float4* bB = bank ? sB1 : sB0;
        const float* Af = (const float*)&bA[m2];
        const float* Bf = (const float*)&bB[m2];
        float sv = sl1(xv.x, -0.5f * Af[h])
                 + sl1(xv.y, -0.5f * Af[2 + h])
                 + sl1(xv.z, -0.5f * Bf[h]);
        if (!act) sv = 0.0f;

        float rs = warpSum(sv);
        if ((tid & 31) == 0) atomicAdd(&g_s[tileW], rs);
    }

    // ---- Stage 5: coord sums (keyed by owned global index u) ----
    {
        int tile = -1;
        float sx0 = 0, sx1 = 0, sx2 = 0, st0 = 0, st1 = 0, st2 = 0;
        if (tid < myU) {
            int u = uStart + tid;
            tile = u >> 10;
            sx0 = px; sx1 = py; sx2 = pz;
            st0 = T[(size_t)u * 3 + 0];
            st1 = T[(size_t)u * 3 + 1];
            st2 = T[(size_t)u * 3 + 2];
        }
        int t0w = __shfl_sync(0xffffffffu, tile, 0);
        bool uni = __all_sync(0xffffffffu, tile == t0w);
        if (uni) {
            if (t0w >= 0) {
                float r0 = warpSum(sx0), r1 = warpSum(sx1), r2 = warpSum(sx2);
                float r3 = warpSum(st0), r4 = warpSum(st1), r5 = warpSum(st2);
                if ((tid & 31) == 0) {
                    atomicAdd(&g_px0[t0w], r0); atomicAdd(&g_px1[t0w], r1); atomicAdd(&g_px2[t0w], r2);
                    atomicAdd(&g_pt0[t0w], r3); atomicAdd(&g_pt1[t0w], r4); atomicAdd(&g_pt2[t0w], r5);
                }
            }
        } else if (tile >= 0) {
            atomicAdd(&g_px0[tile], sx0); atomicAdd(&g_px1[tile], sx1); atomicAdd(&g_px2[tile], sx2);
            atomicAdd(&g_pt0[tile], st0); atomicAdd(&g_pt1[tile], st1); atomicAdd(&g_pt2[tile], st2);
        }
    }

    __syncthreads();
    if (tid == 0) {
        __threadfence();
        unsigned int prev = atomicAdd(&g_count, 1u);
        isLast = (prev == (unsigned int)(gridDim.x - 1)) ? 1 : 0;
    }
    __syncthreads();

    if (isLast && tid < 32) {
        __threadfence();
        float v1 = 0.0f, v2 = 0.0f;
        float invN = 1.0f / (float)NPTS;
        for (int i = tid; i < BT; i += 32) {
            float ss = g_s[i];
            float a0 = g_px0[i], a1 = g_px1[i], a2 = g_px2[i];
            float c0 = g_pt0[i], c1 = g_pt1[i], c2 = g_pt2[i];
            g_s[i] = 0.0f;
            g_px0[i] = 0.0f; g_px1[i] = 0.0f; g_px2[i] = 0.0f;
            g_pt0[i] = 0.0f; g_pt1[i] = 0.0f; g_pt2[i] = 0.0f;
            v1 += W[i] * ss;
            v2 += sl1(a0 * invN, c0 * invN)
                + sl1(a1 * invN, c1 * invN)
                + sl1(a2 * invN, c2 * invN);
        }
        #pragma unroll
        for (int o = 16; o > 0; o >>= 1) {
            v1 += __shfl_down_sync(0xffffffffu, v1, o);
            v2 += __shfl_down_sync(0xffffffffu, v2, o);
        }
        if (tid == 0) {
            out[0] = v1 / (3.0f * (float)NPTS * (float)B);
            out[1] = v2 / ((float)B * 3.0f);
            g_count = 0;
        }
    }
}

extern "C" void kernel_launch(void* const* d_in, const int* in_sizes, int n_in,
                              void* d_out, int out_size)
{
    const float* X = (const float*)d_in[0];   // [B,T,N,3]
    const float* T = (const float*)d_in[1];   // [B,T,N,3]
    const float* W = (const float*)d_in[2];   // [B,T]
    float* out = (float*)d_out;

    const int BT = in_sizes[2];               // 112
    const int B  = 4;

    const int NSM = 148;
    const int totalUnits = BT * NPTS;                     // 114688
    const int unitsPerCta = (totalUnits + NSM - 1) / NSM; // 775

    size_t smem = (size_t)MAXPAIR * 4 * sizeof(float4)    // 2 target banks
                + (size_t)XS_CAP * sizeof(float4)         // sorted preds
                + 1024 * sizeof(int);                     // counters/prefixes
    // smem = 52,224 B > 48KB default: opt in explicitly. Not a stream op,
    // not an allocation -- legal during graph capture, idempotent.
    cudaFuncSetAttribute(nn_loss_kernel,
                         cudaFuncAttributeMaxDynamicSharedMemorySize,
                         (int)smem);
    nn_loss_kernel<<<NSM, 1024, smem>>>(X, T, W, out, BT, B,
                                        totalUnits, unitsPerCta);
}